// round 16
// baseline (speedup 1.0000x reference)
#include <cuda_runtime.h>
#include <cstdint>

// Problem constants
#define NB   32
#define CH   64
#define HH   112
#define WW   112
#define HWSZ (HH*WW)             // 12544
#define PIX  (NB*HWSZ)           // 401408
#define ELEMS (NB*CH*HWSZ)       // 25690112
#define NW   576
#define EPSV 1e-5

// Scratch (device globals only)
__device__ unsigned long long g_xbits[PIX];          // packed activation signs
__device__ unsigned long long g_wpad[CH*10];         // packed weight signs, padded 10/channel
__device__ unsigned char      g_popcw[NW];           // popc per weight word
__device__ short              g_cs[16*CH];           // border correction per pattern x channel
__device__ float              g_scale[CH];           // mean |w| per output channel
__device__ long long          g_S1[CH];              // exact sum of s
__device__ long long          g_S2[CH];              // exact sum of s^2
__device__ short              g_sint[ELEMS];         // conv integer results (NCHW)

// ---------------------------------------------------------------------------
// K0a: weight packing. 1 block, 576 threads.
// ---------------------------------------------------------------------------
__global__ void k0a_pack_w(const float* __restrict__ wflat) {
    __shared__ float abss[NW];
    int t = threadIdx.x;           // 0..575
    int o = t / 9, tap = t % 9;
    unsigned long long bits = 0ull;
    float asum = 0.0f;
    #pragma unroll 8
    for (int i = 0; i < CH; i++) {
        float w = wflat[(o * CH + i) * 9 + tap];
        bits |= (unsigned long long)(__float_as_uint(w) >> 31) << i;
        asum += fabsf(w);
    }
    g_wpad[o * 10 + tap] = bits;
    g_popcw[t] = (unsigned char)__popcll(bits);
    abss[t] = asum;
    __syncthreads();
    if (t < CH) {
        float s = 0.0f;
        #pragma unroll
        for (int j = 0; j < 9; j++) s += abss[t * 9 + j];
        g_scale[t] = s * (1.0f / (float)NW);
        g_S1[t] = 0ll;
        g_S2[t] = 0ll;
        g_wpad[t * 10 + 9] = 0ull;   // padding slot
    }
}

// ---------------------------------------------------------------------------
// K0b: border-correction table. s = nv64 - 2*acc + 2*cs[pat][o].
// pattern bit0=top(h==0), 1=bottom(h==111), 2=left(w==0), 3=right(w==111)
// ---------------------------------------------------------------------------
__global__ void k0b_cs(void) {
    __shared__ unsigned char wps[NW];
    int t = threadIdx.x;
    for (int j = t; j < NW; j += 256) wps[j] = g_popcw[j];
    __syncthreads();
    for (int idx = t; idx < 16 * CH; idx += 256) {
        int p = idx >> 6, o2 = idx & 63;
        unsigned m = 0;
        if (p & 1) m |= 0x007;
        if (p & 2) m |= 0x1C0;
        if (p & 4) m |= 0x049;
        if (p & 8) m |= 0x124;
        int c = 0;
        while (m) { int tt = __ffs(m) - 1; m &= m - 1; c += wps[o2 * 9 + tt]; }
        g_cs[idx] = (short)c;
    }
}

// ---------------------------------------------------------------------------
// K1: pack sign bits of x. 4 pixels per thread, float4 loads per channel.
// ---------------------------------------------------------------------------
__global__ void __launch_bounds__(256) k1_pack(const float* __restrict__ x) {
    int t  = blockIdx.x * 256 + threadIdx.x;       // PIX/4 threads exactly
    int pb = t * 4;
    int n  = pb / HWSZ;
    int hw = pb % HWSZ;
    const float* xp = x + (size_t)n * CH * HWSZ + hw;
    unsigned long long b0 = 0, b1 = 0, b2 = 0, b3 = 0;
    #pragma unroll 8
    for (int c = 0; c < CH; c++) {
        float4 v = *(const float4*)(xp + (size_t)c * HWSZ);
        b0 |= (unsigned long long)(__float_as_uint(v.x) >> 31) << c;
        b1 |= (unsigned long long)(__float_as_uint(v.y) >> 31) << c;
        b2 |= (unsigned long long)(__float_as_uint(v.z) >> 31) << c;
        b3 |= (unsigned long long)(__float_as_uint(v.w) >> 31) << c;
    }
    ulonglong2* dst = (ulonglong2*)(g_xbits + pb);
    dst[0] = make_ulonglong2(b0, b1);
    dst[1] = make_ulonglong2(b2, b3);
}

// ---------------------------------------------------------------------------
// K2: binary conv via xor+popc, stats fused (R15 showed they're ~free).
// 4-way o-split: each thread = 1 pixel x 16 output channels.
// Warp-uniform o-quarter (tid>>6); lanes = 32 consecutive pixels.
// ---------------------------------------------------------------------------
__global__ void __launch_bounds__(256) k2_conv(void) {
    __shared__ __align__(16) unsigned long long ws[CH * 10];
    __shared__ short cs_s[16 * CH];
    __shared__ int bs1[CH], bs2[CH];

    int tid = threadIdx.x;
    #pragma unroll
    for (int j = tid; j < CH * 10; j += 256) ws[j] = g_wpad[j];
    #pragma unroll
    for (int j = tid; j < 16 * CH; j += 256) cs_s[j] = g_cs[j];
    if (tid < CH) { bs1[tid] = 0; bs2[tid] = 0; }
    __syncthreads();

    int q  = tid >> 6;                             // o-quarter 0..3 (warp-uniform)
    int p  = blockIdx.x * 64 + (tid & 63);         // PIX = 6272*64 exact
    int n  = p / HWSZ;
    int hw = p % HWSZ;
    int h  = hw / WW;
    int w  = hw % WW;

    int pat = (h == 0) | ((h == HH - 1) << 1) | ((w == 0) << 2) | ((w == WW - 1) << 3);

    unsigned long long xb[9];
    const unsigned long long* xrow = g_xbits + (size_t)n * HWSZ;
    #pragma unroll
    for (int dh = -1; dh <= 1; dh++) {
        #pragma unroll
        for (int dw = -1; dw <= 1; dw++) {
            int t2 = (dh + 1) * 3 + (dw + 1);
            int hh = h + dh, w2 = w + dw;
            bool valid = (hh >= 0) & (hh < HH) & (w2 >= 0) & (w2 < WW);
            xb[t2] = valid ? xrow[hh * WW + w2] : 0ull;
        }
    }
    int nv64 = 64 * (9 - (!!(pat & 1) + !!(pat & 2) + !!(pat & 4) + !!(pat & 8)) * 3
                       + ((pat & 1) && (pat & 4)) + ((pat & 1) && (pat & 8))
                       + ((pat & 2) && (pat & 4)) + ((pat & 2) && (pat & 8)));
    const short* csrow = cs_s + (pat << 6);
    size_t obase = (size_t)n * CH * HWSZ + hw;
    int lane0 = ((tid & 31) == 0);
    int obeg = q << 4;

    #pragma unroll 4
    for (int oo = 0; oo < 16; oo++) {
        int o = obeg + oo;
        const ulonglong2* wv = (const ulonglong2*)(ws + o * 10);
        ulonglong2 w01 = wv[0], w23 = wv[1], w45 = wv[2], w67 = wv[3];
        unsigned long long w8 = ws[o * 10 + 8];
        int acc = __popcll(xb[0] ^ w01.x) + __popcll(xb[1] ^ w01.y)
                + __popcll(xb[2] ^ w23.x) + __popcll(xb[3] ^ w23.y)
                + __popcll(xb[4] ^ w45.x) + __popcll(xb[5] ^ w45.y)
                + __popcll(xb[6] ^ w67.x) + __popcll(xb[7] ^ w67.y)
                + __popcll(xb[8] ^ w8);
        int s = nv64 - 2 * acc + 2 * (int)csrow[o];
        g_sint[obase + (size_t)o * HWSZ] = (short)s;

        int s1 = __reduce_add_sync(0xffffffffu, s);
        int s2 = __reduce_add_sync(0xffffffffu, s * s);
        if (lane0) { atomicAdd(&bs1[o], s1); atomicAdd(&bs2[o], s2); }
    }
    __syncthreads();
    if (tid < CH) {
        atomicAdd((unsigned long long*)&g_S1[tid], (unsigned long long)(long long)bs1[tid]);
        atomicAdd((unsigned long long*)&g_S2[tid], (unsigned long long)(long long)bs2[tid]);
    }
}

// ---------------------------------------------------------------------------
// K4: BN fold (per-block preamble, exact double) + elementwise epilogue
//     out = s*A[o] + B[o] + x.  8 elems/iter x 4 iters, streaming hints.
// ---------------------------------------------------------------------------
__global__ void __launch_bounds__(256) k4_epilogue(
    const float* __restrict__ x, const float* __restrict__ gamma,
    const float* __restrict__ beta, float* __restrict__ out)
{
    __shared__ float sA[CH], sB[CH];
    int tid = threadIdx.x;
    if (tid < CH) {
        const double cnt = (double)PIX;
        double sc   = (double)g_scale[tid];
        double mean = sc * ((double)g_S1[tid] / cnt);
        double ex2  = sc * sc * ((double)g_S2[tid] / cnt);
        double var  = ex2 - mean * mean;
        double inv  = (double)gamma[tid] * rsqrt(var + EPSV);
        sA[tid] = (float)(sc * inv);
        sB[tid] = (float)((double)beta[tid] - mean * inv);
    }
    __syncthreads();

    int base = blockIdx.x * 1024;                  // ELEMS/8 = 3211264 = 3136*1024
    #pragma unroll 4
    for (int it = 0; it < 4; it++) {
        int i = base + it * 256 + tid;             // 8-elem group
        int o = (i / (HWSZ / 8)) & (CH - 1);
        float a = sA[o], b = sB[o];
        int4  sv = __ldcs((const int4*)g_sint + i);
        float4 x0 = __ldcs((const float4*)x + 2 * i);
        float4 x1 = __ldcs((const float4*)x + 2 * i + 1);
        short2 s0 = *(short2*)&sv.x, s1 = *(short2*)&sv.y;
        short2 s2 = *(short2*)&sv.z, s3 = *(short2*)&sv.w;
        float4 r0, r1;
        r0.x = fmaf((float)s0.x, a, b) + x0.x;
        r0.y = fmaf((float)s0.y, a, b) + x0.y;
        r0.z = fmaf((float)s1.x, a, b) + x0.z;
        r0.w = fmaf((float)s1.y, a, b) + x0.w;
        r1.x = fmaf((float)s2.x, a, b) + x1.x;
        r1.y = fmaf((float)s2.y, a, b) + x1.y;
        r1.z = fmaf((float)s3.x, a, b) + x1.z;
        r1.w = fmaf((float)s3.y, a, b) + x1.w;
        __stcs((float4*)out + 2 * i, r0);
        __stcs((float4*)out + 2 * i + 1, r1);
    }
}

// ---------------------------------------------------------------------------
// Launch order keeps k2 in the 4th (profiled) slot.
// ---------------------------------------------------------------------------
extern "C" void kernel_launch(void* const* d_in, const int* in_sizes, int n_in,
                              void* d_out, int out_size) {
    const float* x     = (const float*)d_in[0];
    const float* wts   = (const float*)d_in[1];
    const float* gamma = (const float*)d_in[2];
    const float* beta  = (const float*)d_in[3];
    float* out = (float*)d_out;

    k0a_pack_w<<<1, NW>>>(wts);
    k1_pack<<<PIX / 4 / 256, 256>>>(x);
    k0b_cs<<<1, 256>>>();
    k2_conv<<<PIX / 64, 256>>>();
    k4_epilogue<<<3136, 256>>>(x, gamma, beta, out);
}

// round 17
// speedup vs baseline: 1.1443x; 1.1443x over previous
#include <cuda_runtime.h>
#include <cstdint>

// Problem constants
#define NB   32
#define CH   64
#define HH   112
#define WW   112
#define HWSZ (HH*WW)             // 12544
#define PIX  (NB*HWSZ)           // 401408
#define ELEMS (NB*CH*HWSZ)       // 25690112
#define NW   576
#define EPSV 1e-5

// Scratch (device globals only)
__device__ unsigned long long g_xbits[PIX];          // packed activation signs
__device__ unsigned long long g_wpad[CH*10];         // packed weight signs, padded 10/channel
__device__ short              g_cs[16*CH];           // border correction per pattern x channel
__device__ float              g_scale[CH];           // mean |w| per output channel
__device__ long long          g_S1[CH];              // exact sum of s
__device__ long long          g_S2[CH];              // exact sum of s^2
__device__ short              g_sint[ELEMS];         // conv integer results (NCHW)

// ---------------------------------------------------------------------------
// K1 fused: blocks 0..391 pack x sign bits (4 px/thread, float4 loads).
// Block 392 does ALL weight prep (pack, scale, stats-zero, cs table) — its
// ~3 us hide entirely under the 392 packing blocks' ~22 us span.
// ---------------------------------------------------------------------------
__global__ void __launch_bounds__(256) k1_fused(const float* __restrict__ x,
                                               const float* __restrict__ wflat) {
    int tid = threadIdx.x;

    if (blockIdx.x == 392) {
        // ---- weight prep (was k0a + k0b) ----
        __shared__ float         abss[NW];
        __shared__ unsigned char wps[NW];
        for (int j = tid; j < NW; j += 256) {
            int o = j / 9, tap = j % 9;
            unsigned long long bits = 0ull;
            float asum = 0.0f;
            #pragma unroll 8
            for (int i = 0; i < CH; i++) {
                float w = wflat[(o * CH + i) * 9 + tap];
                bits |= (unsigned long long)(__float_as_uint(w) >> 31) << i;
                asum += fabsf(w);
            }
            g_wpad[o * 10 + tap] = bits;
            wps[j]  = (unsigned char)__popcll(bits);
            abss[j] = asum;
        }
        __syncthreads();
        if (tid < CH) {
            float s = 0.0f;
            #pragma unroll
            for (int j = 0; j < 9; j++) s += abss[tid * 9 + j];
            g_scale[tid] = s * (1.0f / (float)NW);
            g_S1[tid] = 0ll;
            g_S2[tid] = 0ll;
            g_wpad[tid * 10 + 9] = 0ull;   // padding slot
        }
        // cs table: pattern bit0=top(h==0), 1=bottom, 2=left, 3=right
        for (int idx = tid; idx < 16 * CH; idx += 256) {
            int p = idx >> 6, o2 = idx & 63;
            unsigned m = 0;
            if (p & 1) m |= 0x007;
            if (p & 2) m |= 0x1C0;
            if (p & 4) m |= 0x049;
            if (p & 8) m |= 0x124;
            int c = 0;
            while (m) { int tt = __ffs(m) - 1; m &= m - 1; c += wps[o2 * 9 + tt]; }
            g_cs[idx] = (short)c;
        }
        return;
    }

    // ---- activation sign packing ----
    int t  = blockIdx.x * 256 + tid;               // PIX/4 threads exactly
    int pb = t * 4;
    int n  = pb / HWSZ;
    int hw = pb % HWSZ;
    const float* xp = x + (size_t)n * CH * HWSZ + hw;
    unsigned long long b0 = 0, b1 = 0, b2 = 0, b3 = 0;
    #pragma unroll 8
    for (int c = 0; c < CH; c++) {
        float4 v = *(const float4*)(xp + (size_t)c * HWSZ);
        b0 |= (unsigned long long)(__float_as_uint(v.x) >> 31) << c;
        b1 |= (unsigned long long)(__float_as_uint(v.y) >> 31) << c;
        b2 |= (unsigned long long)(__float_as_uint(v.z) >> 31) << c;
        b3 |= (unsigned long long)(__float_as_uint(v.w) >> 31) << c;
    }
    ulonglong2* dst = (ulonglong2*)(g_xbits + pb);
    dst[0] = make_ulonglong2(b0, b1);
    dst[1] = make_ulonglong2(b2, b3);
}

// ---------------------------------------------------------------------------
// K2: binary conv via xor+popc, stats fused. 2-way o-split (R14 measured-best
// config): each thread = 1 pixel x 32 output channels; warps 0-3 o[0,32),
// warps 4-7 o[32,64).
// ---------------------------------------------------------------------------
__global__ void __launch_bounds__(256) k2_conv(void) {
    __shared__ __align__(16) unsigned long long ws[CH * 10];
    __shared__ short cs_s[16 * CH];
    __shared__ int bs1[CH], bs2[CH];

    int tid = threadIdx.x;
    #pragma unroll
    for (int j = tid; j < CH * 10; j += 256) ws[j] = g_wpad[j];
    #pragma unroll
    for (int j = tid; j < 16 * CH; j += 256) cs_s[j] = g_cs[j];
    if (tid < CH) { bs1[tid] = 0; bs2[tid] = 0; }
    __syncthreads();

    int half = tid >> 7;                           // 0: o in [0,32), 1: [32,64)
    int p  = blockIdx.x * 128 + (tid & 127);       // PIX = 3136*128 exact
    int n  = p / HWSZ;
    int hw = p % HWSZ;
    int h  = hw / WW;
    int w  = hw % WW;

    int pat = (h == 0) | ((h == HH - 1) << 1) | ((w == 0) << 2) | ((w == WW - 1) << 3);

    unsigned long long xb[9];
    const unsigned long long* xrow = g_xbits + (size_t)n * HWSZ;
    #pragma unroll
    for (int dh = -1; dh <= 1; dh++) {
        #pragma unroll
        for (int dw = -1; dw <= 1; dw++) {
            int t2 = (dh + 1) * 3 + (dw + 1);
            int hh = h + dh, w2 = w + dw;
            bool valid = (hh >= 0) & (hh < HH) & (w2 >= 0) & (w2 < WW);
            xb[t2] = valid ? xrow[hh * WW + w2] : 0ull;
        }
    }
    int nv64 = 64 * (9 - (!!(pat & 1) + !!(pat & 2) + !!(pat & 4) + !!(pat & 8)) * 3
                       + ((pat & 1) && (pat & 4)) + ((pat & 1) && (pat & 8))
                       + ((pat & 2) && (pat & 4)) + ((pat & 2) && (pat & 8)));
    const short* csrow = cs_s + (pat << 6);
    size_t obase = (size_t)n * CH * HWSZ + hw;
    int lane0 = ((tid & 31) == 0);
    int obeg = half << 5;

    #pragma unroll 4
    for (int oo = 0; oo < 32; oo++) {
        int o = obeg + oo;
        const ulonglong2* wv = (const ulonglong2*)(ws + o * 10);
        ulonglong2 w01 = wv[0], w23 = wv[1], w45 = wv[2], w67 = wv[3];
        unsigned long long w8 = ws[o * 10 + 8];
        int acc = __popcll(xb[0] ^ w01.x) + __popcll(xb[1] ^ w01.y)
                + __popcll(xb[2] ^ w23.x) + __popcll(xb[3] ^ w23.y)
                + __popcll(xb[4] ^ w45.x) + __popcll(xb[5] ^ w45.y)
                + __popcll(xb[6] ^ w67.x) + __popcll(xb[7] ^ w67.y)
                + __popcll(xb[8] ^ w8);
        int s = nv64 - 2 * acc + 2 * (int)csrow[o];
        g_sint[obase + (size_t)o * HWSZ] = (short)s;

        int s1 = __reduce_add_sync(0xffffffffu, s);
        int s2 = __reduce_add_sync(0xffffffffu, s * s);
        if (lane0) { atomicAdd(&bs1[o], s1); atomicAdd(&bs2[o], s2); }
    }
    __syncthreads();
    if (tid < CH) {
        atomicAdd((unsigned long long*)&g_S1[tid], (unsigned long long)(long long)bs1[tid]);
        atomicAdd((unsigned long long*)&g_S2[tid], (unsigned long long)(long long)bs2[tid]);
    }
}

// ---------------------------------------------------------------------------
// K4: BN fold (per-block preamble, exact double) + elementwise epilogue
//     out = s*A[o] + B[o] + x.  8 elems/iter x 4 iters, streaming hints.
// ---------------------------------------------------------------------------
__global__ void __launch_bounds__(256) k4_epilogue(
    const float* __restrict__ x, const float* __restrict__ gamma,
    const float* __restrict__ beta, float* __restrict__ out)
{
    __shared__ float sA[CH], sB[CH];
    int tid = threadIdx.x;
    if (tid < CH) {
        const double cnt = (double)PIX;
        double sc   = (double)g_scale[tid];
        double mean = sc * ((double)g_S1[tid] / cnt);
        double ex2  = sc * sc * ((double)g_S2[tid] / cnt);
        double var  = ex2 - mean * mean;
        double inv  = (double)gamma[tid] * rsqrt(var + EPSV);
        sA[tid] = (float)(sc * inv);
        sB[tid] = (float)((double)beta[tid] - mean * inv);
    }
    __syncthreads();

    int base = blockIdx.x * 1024;                  // ELEMS/8 = 3211264 = 3136*1024
    #pragma unroll 4
    for (int it = 0; it < 4; it++) {
        int i = base + it * 256 + tid;             // 8-elem group
        int o = (i / (HWSZ / 8)) & (CH - 1);
        float a = sA[o], b = sB[o];
        int4  sv = __ldcs((const int4*)g_sint + i);
        float4 x0 = __ldcs((const float4*)x + 2 * i);
        float4 x1 = __ldcs((const float4*)x + 2 * i + 1);
        short2 s0 = *(short2*)&sv.x, s1 = *(short2*)&sv.y;
        short2 s2 = *(short2*)&sv.z, s3 = *(short2*)&sv.w;
        float4 r0, r1;
        r0.x = fmaf((float)s0.x, a, b) + x0.x;
        r0.y = fmaf((float)s0.y, a, b) + x0.y;
        r0.z = fmaf((float)s1.x, a, b) + x0.z;
        r0.w = fmaf((float)s1.y, a, b) + x0.w;
        r1.x = fmaf((float)s2.x, a, b) + x1.x;
        r1.y = fmaf((float)s2.y, a, b) + x1.y;
        r1.z = fmaf((float)s3.x, a, b) + x1.z;
        r1.w = fmaf((float)s3.y, a, b) + x1.w;
        __stcs((float4*)out + 2 * i, r0);
        __stcs((float4*)out + 2 * i + 1, r1);
    }
}

// ---------------------------------------------------------------------------
// 3 launches total: weight prep rides inside k1 as an extra block.
// ---------------------------------------------------------------------------
extern "C" void kernel_launch(void* const* d_in, const int* in_sizes, int n_in,
                              void* d_out, int out_size) {
    const float* x     = (const float*)d_in[0];
    const float* wts   = (const float*)d_in[1];
    const float* gamma = (const float*)d_in[2];
    const float* beta  = (const float*)d_in[3];
    float* out = (float*)d_out;

    k1_fused<<<393, 256>>>(x, wts);
    k2_conv<<<PIX / 128, 256>>>();
    k4_epilogue<<<3136, 256>>>(x, gamma, beta, out);
}